// round 9
// baseline (speedup 1.0000x reference)
#include <cuda_runtime.h>
#include <cstddef>

typedef unsigned long long u64;

// Scratch (static __device__ — no allocations allowed).
__device__ float g_S[1966080];    // softmaxed weights, all 4 layers
__device__ float g_hA[2097152];   // 512*256*16 (layer1 out, reused by layer3 out)
__device__ float g_hB[1048576];   // 512*128*16 (layer2 out, reused by layer4 out)

// ---------------- packed f32x2 helpers (dual-fp32 pipe) --------------------
__device__ __forceinline__ void fma2(u64& d, u64 a, u64 b) {
    asm("fma.rn.f32x2 %0, %1, %2, %0;" : "+l"(d) : "l"(a), "l"(b));
}
__device__ __forceinline__ u64 add2(u64 a, u64 b) {
    u64 d; asm("add.rn.f32x2 %0, %1, %2;" : "=l"(d) : "l"(a), "l"(b)); return d;
}
__device__ __forceinline__ u64 pack2(float x) {
    u64 d; asm("mov.b64 %0, {%1, %1};" : "=l"(d) : "f"(x)); return d;
}
__device__ __forceinline__ void unpack2(u64 a, float& lo, float& hi) {
    asm("mov.b64 {%0, %1}, %2;" : "=f"(lo), "=f"(hi) : "l"(a));
}

// ---------------------------------------------------------------------------
// Kernel 1: weight softmax. One block per f-slice (480 blocks, 256 threads).
// ---------------------------------------------------------------------------
__global__ void __launch_bounds__(256) wsoftmax_kernel(
    const float* __restrict__ W1, const float* __restrict__ W2,
    const float* __restrict__ W3, const float* __restrict__ W4)
{
    __shared__ float Ssm[4096];
    __shared__ float red[256];
    __shared__ float mxk[16];

    const int bx = blockIdx.x;
    const int t  = threadIdx.x;
    const float* W; float* S; int f;
    if (bx < 256)      { W = W1; S = g_S;           f = bx;       }
    else if (bx < 384) { W = W2; S = g_S + 1048576; f = bx - 256; }
    else if (bx < 448) { W = W3; S = g_S + 1572864; f = bx - 384; }
    else               { W = W4; S = g_S + 1835008; f = bx - 448; }

    const float4* Wg = (const float4*)(W + (size_t)f * 4096);
    float4*       Sg = (float4*)(S + (size_t)f * 4096);

    #pragma unroll
    for (int q = 0; q < 4; q++) ((float4*)Ssm)[t + 256 * q] = Wg[t + 256 * q];
    __syncthreads();

    const int k = t & 15;
    const int g = t >> 4;

    float pm = -1e30f;
    #pragma unroll
    for (int mm = 0; mm < 16; mm++) pm = fmaxf(pm, Ssm[(g * 16 + mm) * 16 + k]);
    red[g * 16 + k] = pm;
    __syncthreads();
    #pragma unroll
    for (int st = 8; st > 0; st >>= 1) {
        if (g < st) red[g * 16 + k] = fmaxf(red[g * 16 + k], red[(g + st) * 16 + k]);
        __syncthreads();
    }
    if (g == 0) mxk[k] = red[k];
    __syncthreads();

    const float mx = mxk[k];
    float ps = 0.f;
    #pragma unroll
    for (int mm = 0; mm < 16; mm++) {
        int idx = (g * 16 + mm) * 16 + k;
        float e = __expf(Ssm[idx] - mx);
        Ssm[idx] = e;
        ps += e;
    }
    __syncthreads();
    red[g * 16 + k] = ps;
    __syncthreads();
    #pragma unroll
    for (int st = 8; st > 0; st >>= 1) {
        if (g < st) red[g * 16 + k] += red[(g + st) * 16 + k];
        __syncthreads();
    }
    const float inv = 1.f / red[k];
    #pragma unroll
    for (int mm = 0; mm < 16; mm++) Ssm[(g * 16 + mm) * 16 + k] *= inv;
    __syncthreads();

    #pragma unroll
    for (int q = 0; q < 4; q++) Sg[t + 256 * q] = ((float4*)Ssm)[t + 256 * q];
}

// ---------------------------------------------------------------------------
// store one k-quad: log + base, float4 store.
// ---------------------------------------------------------------------------
__device__ __forceinline__ void store_quad(float* dst, u64 lo, u64 hi, float base) {
    float x0, x1, x2, x3;
    unpack2(lo, x0, x1);
    unpack2(hi, x2, x3);
    *(float4*)dst = make_float4(__logf(x0) + base, __logf(x1) + base,
                                __logf(x2) + base, __logf(x3) + base);
}

// ---------------------------------------------------------------------------
// Kernel 2: one SPN layer. m-split over i (MS lanes, XOR-swizzled S), NT
// samples per thread. 128 threads = NSL n-slots x MS i-lanes; thread (nl,si)
// owns i in [G*si, G*si+G), G = 16/MS, all 16 k, samples n0 (+n1 = n0+NSL).
// S layout: float4 of (m, quad q) at m*16 + 4*(q ^ (si(i)&3)): si-lanes read
// distinct quads (disjoint banks, LDS.128), nl-lanes broadcast. acc[2q+t]
// holds logical quad q^(si&3); shfl-xor reduce uses partner register u^(2r).
// Instruction count is MS-invariant -> raising MS multiplies grid for free.
// launch_bounds(128,7): 7 blocks/SM -> 1024-block grids fit in ONE wave.
// ---------------------------------------------------------------------------
template<int MS, int NT, int MINB>
__global__ void __launch_bounds__(128, MINB) layer_kernel(
    const float* __restrict__ hin, const float* __restrict__ Sall,
    float* __restrict__ hout, int F_in, int s_off)
{
    constexpr int G   = 16 / MS;               // i-values per thread
    constexpr int NSL = 128 / MS;              // n-slots per block
    constexpr int LG  = (G == 16) ? 4 : (G == 8) ? 3 : (G == 4) ? 2 : 1;
    constexpr int XRM = (MS < 4 ? MS : 4) - 1; // quad-xor mask
    constexpr int UJ  = (MS <= 2) ? 2 : 4;     // j-unroll
    constexpr int BSTR = 17 * NT;

    extern __shared__ float sm[];
    float* Ssm   = sm;                          // 4096 floats (swizzled)
    float* Brows = sm + 4096;                   // NSL rows of BSTR

    const int tid = threadIdx.x;
    const int si  = tid & (MS - 1);
    const int nl  = tid / MS;
    const int f   = blockIdx.x;
    const int F_out = F_in >> 1;
    const int n0 = blockIdx.y * (NT * NSL) + nl;
    const int n1 = n0 + NSL;
    const int xr = si & XRM;

    // Stage S_f with quad swizzle, coalesced global reads.
    {
        const float4* Sg = (const float4*)(Sall + (size_t)s_off + (size_t)f * 4096);
        #pragma unroll
        for (int q8 = 0; q8 < 8; q8++) {
            const int idx = tid + 128 * q8;
            float4 v = Sg[idx];
            if constexpr (MS == 1) {
                ((float4*)Ssm)[idx] = v;
            } else {
                const int m = idx >> 2, k4 = idx & 3;
                const int xi = (m >> (4 + LG)) & XRM;  // si(i) & XRM
                *(float4*)(Ssm + m * 16 + 4 * (k4 ^ xi)) = v;
            }
        }
    }

    // Prologue: each thread globally loads only its i-slices; maxes via shfl.
    float a0[G], a1[G];
    float base0 = 0.f, base1 = 0.f;
    float* row = Brows + nl * BSTR;
    {
        float av[G], bv[G];
        const float* h0 = hin + ((size_t)n0 * F_in + 2 * f) * 16 + G * si;
        if constexpr (G >= 4) {
            #pragma unroll
            for (int c = 0; c < G / 4; c++) {
                ((float4*)av)[c] = *(const float4*)(h0 + 4 * c);
                ((float4*)bv)[c] = *(const float4*)(h0 + 16 + 4 * c);
            }
        } else {
            ((float2*)av)[0] = *(const float2*)(h0);
            ((float2*)bv)[0] = *(const float2*)(h0 + 16);
        }
        float l = av[0], r = bv[0];
        #pragma unroll
        for (int d = 1; d < G; d++) { l = fmaxf(l, av[d]); r = fmaxf(r, bv[d]); }
        #pragma unroll
        for (int rr = 1; rr < MS; rr <<= 1) {
            l = fmaxf(l, __shfl_xor_sync(0xffffffffu, l, rr));
            r = fmaxf(r, __shfl_xor_sync(0xffffffffu, r, rr));
        }
        #pragma unroll
        for (int d = 0; d < G; d++) {
            a0[d] = __expf(av[d] - l);
            row[NT * (G * si + d)] = __expf(bv[d] - r);
        }
        base0 = l + r;
    }
    if constexpr (NT == 2) {
        float av[G], bv[G];
        const float* h1 = hin + ((size_t)n1 * F_in + 2 * f) * 16 + G * si;
        if constexpr (G >= 4) {
            #pragma unroll
            for (int c = 0; c < G / 4; c++) {
                ((float4*)av)[c] = *(const float4*)(h1 + 4 * c);
                ((float4*)bv)[c] = *(const float4*)(h1 + 16 + 4 * c);
            }
        } else {
            ((float2*)av)[0] = *(const float2*)(h1);
            ((float2*)bv)[0] = *(const float2*)(h1 + 16);
        }
        float l = av[0], r = bv[0];
        #pragma unroll
        for (int d = 1; d < G; d++) { l = fmaxf(l, av[d]); r = fmaxf(r, bv[d]); }
        #pragma unroll
        for (int rr = 1; rr < MS; rr <<= 1) {
            l = fmaxf(l, __shfl_xor_sync(0xffffffffu, l, rr));
            r = fmaxf(r, __shfl_xor_sync(0xffffffffu, r, rr));
        }
        #pragma unroll
        for (int d = 0; d < G; d++) {
            a1[d] = __expf(av[d] - l);
            row[2 * (G * si + d) + 1] = __expf(bv[d] - r);
        }
        base1 = l + r;
    }
    __syncthreads();

    // Mainloop. acc[2q+t] = logical quad (q^xr), halves t (k-pairs).
    u64 acc0[8], acc1[8];
    #pragma unroll
    for (int u = 0; u < 8; u++) { acc0[u] = 0ull; acc1[u] = 0ull; }

    const float* pq0 = Ssm + si * (G * 256) + 4 * (0 ^ xr);
    const float* pq1 = Ssm + si * (G * 256) + 4 * (1 ^ xr);
    const float* pq2 = Ssm + si * (G * 256) + 4 * (2 ^ xr);
    const float* pq3 = Ssm + si * (G * 256) + 4 * (3 ^ xr);

    #pragma unroll UJ
    for (int j = 0; j < 16; j++) {
        float b0, b1;
        if constexpr (NT == 2) {
            unpack2(((const u64*)row)[j], b0, b1);
        } else {
            b0 = row[j];
        }
        const int jo = j * 16;
        #pragma unroll
        for (int d = 0; d < G; d++) {
            const int o = d * 256 + jo;
            const u64 p0 = pack2(a0[d] * b0);
            u64 p1 = 0ull;
            if constexpr (NT == 2) p1 = pack2(a1[d] * b1);
            ulonglong2 w;
            w = *(const ulonglong2*)(pq0 + o);
            fma2(acc0[0], p0, w.x); fma2(acc0[1], p0, w.y);
            if constexpr (NT == 2) { fma2(acc1[0], p1, w.x); fma2(acc1[1], p1, w.y); }
            w = *(const ulonglong2*)(pq1 + o);
            fma2(acc0[2], p0, w.x); fma2(acc0[3], p0, w.y);
            if constexpr (NT == 2) { fma2(acc1[2], p1, w.x); fma2(acc1[3], p1, w.y); }
            w = *(const ulonglong2*)(pq2 + o);
            fma2(acc0[4], p0, w.x); fma2(acc0[5], p0, w.y);
            if constexpr (NT == 2) { fma2(acc1[4], p1, w.x); fma2(acc1[5], p1, w.y); }
            w = *(const ulonglong2*)(pq3 + o);
            fma2(acc0[6], p0, w.x); fma2(acc0[7], p0, w.y);
            if constexpr (NT == 2) { fma2(acc1[6], p1, w.x); fma2(acc1[7], p1, w.y); }
        }
    }

    // Reduce across si lanes. Round r: partner register u^(2r) (r<4), u (r=4).
    if constexpr (MS >= 2) {
        u64 t0[8], t1[8];
        #pragma unroll
        for (int u = 0; u < 8; u++) {
            t0[u] = __shfl_xor_sync(0xffffffffu, acc0[u ^ 2], 1);
            if constexpr (NT == 2) t1[u] = __shfl_xor_sync(0xffffffffu, acc1[u ^ 2], 1);
        }
        #pragma unroll
        for (int u = 0; u < 8; u++) {
            acc0[u] = add2(acc0[u], t0[u]);
            if constexpr (NT == 2) acc1[u] = add2(acc1[u], t1[u]);
        }
    }
    if constexpr (MS >= 4) {
        u64 t0[8], t1[8];
        #pragma unroll
        for (int u = 0; u < 8; u++) {
            t0[u] = __shfl_xor_sync(0xffffffffu, acc0[u ^ 4], 2);
            if constexpr (NT == 2) t1[u] = __shfl_xor_sync(0xffffffffu, acc1[u ^ 4], 2);
        }
        #pragma unroll
        for (int u = 0; u < 8; u++) {
            acc0[u] = add2(acc0[u], t0[u]);
            if constexpr (NT == 2) acc1[u] = add2(acc1[u], t1[u]);
        }
    }
    if constexpr (MS == 8) {
        u64 t0[8], t1[8];
        #pragma unroll
        for (int u = 0; u < 8; u++) {
            t0[u] = __shfl_xor_sync(0xffffffffu, acc0[u], 4);
            if constexpr (NT == 2) t1[u] = __shfl_xor_sync(0xffffffffu, acc1[u], 4);
        }
        #pragma unroll
        for (int u = 0; u < 8; u++) {
            acc0[u] = add2(acc0[u], t0[u]);
            if constexpr (NT == 2) acc1[u] = add2(acc1[u], t1[u]);
        }
    }

    // Store.
    float* o0p = hout + ((size_t)n0 * F_out + f) * 16;
    float* o1p = hout + ((size_t)n1 * F_out + f) * 16;
    if constexpr (MS == 1) {
        #pragma unroll
        for (int q = 0; q < 4; q++) {
            store_quad(o0p + 4 * q, acc0[2 * q], acc0[2 * q + 1], base0);
            if constexpr (NT == 2)
                store_quad(o1p + 4 * q, acc1[2 * q], acc1[2 * q + 1], base1);
        }
    } else if constexpr (MS == 2) {
        const int ka = si ? 12 : 0, kb = si ? 8 : 4;
        u64 A0 = si ? acc0[4] : acc0[0], A1 = si ? acc0[5] : acc0[1];
        u64 B0 = si ? acc0[6] : acc0[2], B1 = si ? acc0[7] : acc0[3];
        store_quad(o0p + ka, A0, A1, base0);
        store_quad(o0p + kb, B0, B1, base0);
        if constexpr (NT == 2) {
            u64 C0 = si ? acc1[4] : acc1[0], C1 = si ? acc1[5] : acc1[1];
            u64 D0 = si ? acc1[6] : acc1[2], D1 = si ? acc1[7] : acc1[3];
            store_quad(o1p + ka, C0, C1, base1);
            store_quad(o1p + kb, D0, D1, base1);
        }
    } else if constexpr (MS == 4) {
        store_quad(o0p + 4 * si, acc0[0], acc0[1], base0);
        if constexpr (NT == 2)
            store_quad(o1p + 4 * si, acc1[0], acc1[1], base1);
    } else { // MS == 8: lanes 0-3 carry distinct logical quads (si&3)
        if (si < 4) {
            store_quad(o0p + 4 * si, acc0[0], acc0[1], base0);
            if constexpr (NT == 2)
                store_quad(o1p + 4 * si, acc1[0], acc1[1], base1);
        }
    }
}

// ---------------------------------------------------------------------------
// Kernel 3: root. Block per n (512 blocks, 32 threads), warp-shfl reduce.
// ---------------------------------------------------------------------------
__global__ void __launch_bounds__(32) root_kernel(
    const float* __restrict__ h4, const float* __restrict__ Wroot,
    float* __restrict__ out)
{
    const int n = blockIdx.x;
    const int t = threadIdx.x;
    const float4* hp = (const float4*)(h4 + (size_t)n * 512);

    float4 a = make_float4(0.f, 0.f, 0.f, 0.f);
    #pragma unroll
    for (int r = 0; r < 4; r++) {
        float4 q = hp[t + 32 * r];
        a.x += q.x; a.y += q.y; a.z += q.z; a.w += q.w;
    }
    #pragma unroll
    for (int st = 4; st <= 16; st <<= 1) {
        a.x += __shfl_xor_sync(0xffffffffu, a.x, st);
        a.y += __shfl_xor_sync(0xffffffffu, a.y, st);
        a.z += __shfl_xor_sync(0xffffffffu, a.z, st);
        a.w += __shfl_xor_sync(0xffffffffu, a.w, st);
    }
    __shared__ float sred[16];
    if (t < 4) { sred[4*t] = a.x; sred[4*t+1] = a.y; sred[4*t+2] = a.z; sred[4*t+3] = a.w; }
    __syncwarp();

    if (t == 0) {
        float w[16];
        #pragma unroll
        for (int k = 0; k < 16; k++) w[k] = Wroot[k];
        float wm = w[0];
        #pragma unroll
        for (int k = 1; k < 16; k++) wm = fmaxf(wm, w[k]);
        float Z = 0.f;
        #pragma unroll
        for (int k = 0; k < 16; k++) Z += __expf(w[k] - wm);
        const float lz = __logf(Z) + wm;

        float tv[16];
        float tm = -1e30f;
        #pragma unroll
        for (int k = 0; k < 16; k++) {
            tv[k] = sred[k] + w[k] - lz;
            tm = fmaxf(tm, tv[k]);
        }
        float ss = 0.f;
        #pragma unroll
        for (int k = 0; k < 16; k++) ss += __expf(tv[k] - tm);
        out[n] = __logf(ss) + tm;
    }
}

// ---------------------------------------------------------------------------
extern "C" void kernel_launch(void* const* d_in, const int* in_sizes, int n_in,
                              void* d_out, int out_size)
{
    const float* x  = (const float*)d_in[0];
    const float* W1 = (const float*)d_in[1];
    const float* W2 = (const float*)d_in[2];
    const float* W3 = (const float*)d_in[3];
    const float* W4 = (const float*)d_in[4];
    const float* Wr = (const float*)d_in[5];
    float* out = (float*)d_out;

    float *S, *hA, *hB;
    cudaGetSymbolAddress((void**)&S,  g_S);
    cudaGetSymbolAddress((void**)&hA, g_hA);
    cudaGetSymbolAddress((void**)&hB, g_hB);

    wsoftmax_kernel<<<480, 256>>>(W1, W2, W3, W4);

    // smem = 16KB (S) + NSL*17*NT*4 (b rows).
    const size_t smL1 = 16384 + 64 * 34 * 4;  // MS=2, NT=2: 25088
    const size_t smL2 = 16384 + 32 * 34 * 4;  // MS=4, NT=2: 20736
    const size_t smL3 = 16384 + 32 * 17 * 4;  // MS=4, NT=1: 18560
    const size_t smL4 = 16384 + 16 * 34 * 4;  // MS=8, NT=2: 18560

    // L1-L3: 1024 blocks, single wave at 7 blocks/SM (occ 43%). L4: 512.
    layer_kernel<2, 2, 7><<<dim3(256, 4),  128, smL1>>>(x,  S, hA, 512, 0);
    layer_kernel<4, 2, 7><<<dim3(128, 8),  128, smL2>>>(hA, S, hB, 256, 1048576);
    layer_kernel<4, 1, 7><<<dim3(64, 16),  128, smL3>>>(hB, S, hA, 128, 1572864);
    layer_kernel<8, 2, 7><<<dim3(32, 16),  128, smL4>>>(hA, S, hB, 64,  1835008);

    root_kernel<<<512, 32>>>(hB, Wr, out);
}

// round 11
// speedup vs baseline: 1.1187x; 1.1187x over previous
#include <cuda_runtime.h>
#include <cstddef>

typedef unsigned long long u64;

// Scratch (static __device__ — no allocations allowed).
__device__ float g_hA[2097152];   // 512*256*16 (layer1 out, reused by layer3 out)
__device__ float g_hB[1048576];   // 512*128*16 (layer2 out, reused by layer4 out)

// ---------------- packed f32x2 helpers (dual-fp32 pipe) --------------------
__device__ __forceinline__ void fma2(u64& d, u64 a, u64 b) {
    asm("fma.rn.f32x2 %0, %1, %2, %0;" : "+l"(d) : "l"(a), "l"(b));
}
__device__ __forceinline__ u64 add2(u64 a, u64 b) {
    u64 d; asm("add.rn.f32x2 %0, %1, %2;" : "=l"(d) : "l"(a), "l"(b)); return d;
}
__device__ __forceinline__ u64 pack2(float x) {
    u64 d; asm("mov.b64 %0, {%1, %1};" : "=l"(d) : "f"(x)); return d;
}
__device__ __forceinline__ void unpack2(u64 a, float& lo, float& hi) {
    asm("mov.b64 {%0, %1}, %2;" : "=f"(lo), "=f"(hi) : "l"(a));
}

// store one k-quad: log + base, float4 store (R8 form — S is normalized).
__device__ __forceinline__ void store_quad(float* dst, u64 lo, u64 hi, float base) {
    float x0, x1, x2, x3;
    unpack2(lo, x0, x1);
    unpack2(hi, x2, x3);
    *(float4*)dst = make_float4(__logf(x0) + base, __logf(x1) + base,
                                __logf(x2) + base, __logf(x3) + base);
}

// ---------------------------------------------------------------------------
// One SPN layer with FUSED, fully-NORMALIZED weight softmax.
//   Downstream compute is EXACTLY R8 (best passing config): m-split over i
//   (MS lanes, XOR-swizzled S, broadcast LDS.128), NT=2 samples/thread,
//   512-block grids.
//   Softmax preamble (replaces the separate wsoftmax kernel + g_S):
//     1) stage raw W_f into regs (8 float4/thread, coalesced — replaces the
//        former g_S load, so no added smem/global traffic),
//     2) per-k colmax: stride-4 shfl butterfly + cross-warp smem reduce,
//     3) exp in regs + colsum (same reduction pattern),
//     4) multiply by 1/colsum, store swizzled — smem S content is then
//        IDENTICAL to what R8 read from g_S. No epilogue correction needed.
// ---------------------------------------------------------------------------
template<int MS>
__global__ void __launch_bounds__(128) layer_kernel(
    const float* __restrict__ hin, const float* __restrict__ Wl,
    float* __restrict__ hout, int F_in)
{
    constexpr int G    = 16 / MS;               // i-values per thread
    constexpr int NSL  = 128 / MS;              // n-slots per block
    constexpr int LG   = (G == 16) ? 4 : (G == 8) ? 3 : (G == 4) ? 2 : 1;
    constexpr int XRM  = (MS < 4 ? MS : 4) - 1; // quad-xor mask
    constexpr int UJ   = (MS <= 2) ? 2 : 4;     // j-unroll
    constexpr int REDA = 4096;                  // colmax cross-warp (64 f)
    constexpr int REDB = 4160;                  // colsum cross-warp (64 f)
    constexpr int BR   = 4224;                  // b rows (NSL * 34)

    extern __shared__ float sm[];
    float* Ssm   = sm;                          // 4096 floats (swizzled S)
    float* Brows = sm + BR;

    const int tid  = threadIdx.x;
    const int si   = tid & (MS - 1);
    const int nl   = tid / MS;
    const int f    = blockIdx.x;
    const int F_out = F_in >> 1;
    const int n0   = blockIdx.y * (2 * NSL) + nl;
    const int n1   = n0 + NSL;
    const int xr   = si & XRM;
    const int q    = tid & 3;                   // this thread's k-quad
    const int wid  = tid >> 5;
    const int lane = tid & 31;

    // ---- Fused weight softmax (fully normalized) -----------------------
    float4 wreg[8];
    {
        const float4* Wg = (const float4*)(Wl + (size_t)f * 4096);
        #pragma unroll
        for (int s8 = 0; s8 < 8; s8++) wreg[s8] = Wg[tid + 128 * s8];
    }
    // per-thread colmax partial (k-quad q, this thread's 8 m's)
    float4 mx4 = wreg[0];
    #pragma unroll
    for (int s8 = 1; s8 < 8; s8++) {
        mx4.x = fmaxf(mx4.x, wreg[s8].x); mx4.y = fmaxf(mx4.y, wreg[s8].y);
        mx4.z = fmaxf(mx4.z, wreg[s8].z); mx4.w = fmaxf(mx4.w, wreg[s8].w);
    }
    #pragma unroll
    for (int off = 4; off < 32; off <<= 1) {
        mx4.x = fmaxf(mx4.x, __shfl_xor_sync(0xffffffffu, mx4.x, off));
        mx4.y = fmaxf(mx4.y, __shfl_xor_sync(0xffffffffu, mx4.y, off));
        mx4.z = fmaxf(mx4.z, __shfl_xor_sync(0xffffffffu, mx4.z, off));
        mx4.w = fmaxf(mx4.w, __shfl_xor_sync(0xffffffffu, mx4.w, off));
    }
    if (lane < 4) *(float4*)(sm + REDA + wid * 16 + q * 4) = mx4;
    __syncthreads();
    {
        mx4 = *(const float4*)(sm + REDA + q * 4);
        #pragma unroll
        for (int w = 1; w < 4; w++) {
            float4 t = *(const float4*)(sm + REDA + w * 16 + q * 4);
            mx4.x = fmaxf(mx4.x, t.x); mx4.y = fmaxf(mx4.y, t.y);
            mx4.z = fmaxf(mx4.z, t.z); mx4.w = fmaxf(mx4.w, t.w);
        }
    }
    // exp IN REGISTERS + colsum partial (no store yet)
    float4 sum4 = make_float4(0.f, 0.f, 0.f, 0.f);
    #pragma unroll
    for (int s8 = 0; s8 < 8; s8++) {
        wreg[s8].x = __expf(wreg[s8].x - mx4.x);
        wreg[s8].y = __expf(wreg[s8].y - mx4.y);
        wreg[s8].z = __expf(wreg[s8].z - mx4.z);
        wreg[s8].w = __expf(wreg[s8].w - mx4.w);
        sum4.x += wreg[s8].x; sum4.y += wreg[s8].y;
        sum4.z += wreg[s8].z; sum4.w += wreg[s8].w;
    }
    #pragma unroll
    for (int off = 4; off < 32; off <<= 1) {
        sum4.x += __shfl_xor_sync(0xffffffffu, sum4.x, off);
        sum4.y += __shfl_xor_sync(0xffffffffu, sum4.y, off);
        sum4.z += __shfl_xor_sync(0xffffffffu, sum4.z, off);
        sum4.w += __shfl_xor_sync(0xffffffffu, sum4.w, off);
    }
    if (lane < 4) *(float4*)(sm + REDB + wid * 16 + q * 4) = sum4;
    __syncthreads();
    {
        sum4 = *(const float4*)(sm + REDB + q * 4);
        #pragma unroll
        for (int w = 1; w < 4; w++) {
            float4 t = *(const float4*)(sm + REDB + w * 16 + q * 4);
            sum4.x += t.x; sum4.y += t.y; sum4.z += t.z; sum4.w += t.w;
        }
    }
    const float4 inv4 = make_float4(1.f / sum4.x, 1.f / sum4.y,
                                    1.f / sum4.z, 1.f / sum4.w);
    // normalized store, swizzled — EXACTLY R8's g_S content & layout
    #pragma unroll
    for (int s8 = 0; s8 < 8; s8++) {
        const int idx = tid + 128 * s8;
        const int m = idx >> 2;
        float4 e = make_float4(wreg[s8].x * inv4.x, wreg[s8].y * inv4.y,
                               wreg[s8].z * inv4.z, wreg[s8].w * inv4.w);
        const int xi = (m >> (4 + LG)) & XRM;
        *(float4*)(Ssm + m * 16 + 4 * (q ^ xi)) = e;
    }

    // ---- Prologue (identical to R8): children -> maxes, exps -----------
    float a0[G], a1[G];
    float base0, base1;
    float* row = Brows + nl * 34;
    {
        float av[G], bv[G];
        const float* h0 = hin + ((size_t)n0 * F_in + 2 * f) * 16 + G * si;
        if constexpr (G >= 4) {
            #pragma unroll
            for (int c = 0; c < G / 4; c++) {
                ((float4*)av)[c] = *(const float4*)(h0 + 4 * c);
                ((float4*)bv)[c] = *(const float4*)(h0 + 16 + 4 * c);
            }
        } else {
            ((float2*)av)[0] = *(const float2*)(h0);
            ((float2*)bv)[0] = *(const float2*)(h0 + 16);
        }
        float l = av[0], r = bv[0];
        #pragma unroll
        for (int d = 1; d < G; d++) { l = fmaxf(l, av[d]); r = fmaxf(r, bv[d]); }
        #pragma unroll
        for (int rr = 1; rr < MS; rr <<= 1) {
            l = fmaxf(l, __shfl_xor_sync(0xffffffffu, l, rr));
            r = fmaxf(r, __shfl_xor_sync(0xffffffffu, r, rr));
        }
        #pragma unroll
        for (int d = 0; d < G; d++) {
            a0[d] = __expf(av[d] - l);
            row[2 * (G * si + d)] = __expf(bv[d] - r);
        }
        base0 = l + r;
    }
    {
        float av[G], bv[G];
        const float* h1 = hin + ((size_t)n1 * F_in + 2 * f) * 16 + G * si;
        if constexpr (G >= 4) {
            #pragma unroll
            for (int c = 0; c < G / 4; c++) {
                ((float4*)av)[c] = *(const float4*)(h1 + 4 * c);
                ((float4*)bv)[c] = *(const float4*)(h1 + 16 + 4 * c);
            }
        } else {
            ((float2*)av)[0] = *(const float2*)(h1);
            ((float2*)bv)[0] = *(const float2*)(h1 + 16);
        }
        float l = av[0], r = bv[0];
        #pragma unroll
        for (int d = 1; d < G; d++) { l = fmaxf(l, av[d]); r = fmaxf(r, bv[d]); }
        #pragma unroll
        for (int rr = 1; rr < MS; rr <<= 1) {
            l = fmaxf(l, __shfl_xor_sync(0xffffffffu, l, rr));
            r = fmaxf(r, __shfl_xor_sync(0xffffffffu, r, rr));
        }
        #pragma unroll
        for (int d = 0; d < G; d++) {
            a1[d] = __expf(av[d] - l);
            row[2 * (G * si + d) + 1] = __expf(bv[d] - r);
        }
        base1 = l + r;
    }
    __syncthreads();   // Ssm and b-rows ready

    // ---- Mainloop (identical to R8) ------------------------------------
    u64 acc0[8], acc1[8];
    #pragma unroll
    for (int u = 0; u < 8; u++) { acc0[u] = 0ull; acc1[u] = 0ull; }

    const float* pq0 = Ssm + si * (G * 256) + 4 * (0 ^ xr);
    const float* pq1 = Ssm + si * (G * 256) + 4 * (1 ^ xr);
    const float* pq2 = Ssm + si * (G * 256) + 4 * (2 ^ xr);
    const float* pq3 = Ssm + si * (G * 256) + 4 * (3 ^ xr);
    const u64* rowq = (const u64*)row;

    #pragma unroll UJ
    for (int j = 0; j < 16; j++) {
        float b0, b1;
        unpack2(rowq[j], b0, b1);
        const int jo = j * 16;
        #pragma unroll
        for (int d = 0; d < G; d++) {
            const int o = d * 256 + jo;
            const u64 p0 = pack2(a0[d] * b0);
            const u64 p1 = pack2(a1[d] * b1);
            ulonglong2 w;
            w = *(const ulonglong2*)(pq0 + o);
            fma2(acc0[0], p0, w.x); fma2(acc0[1], p0, w.y);
            fma2(acc1[0], p1, w.x); fma2(acc1[1], p1, w.y);
            w = *(const ulonglong2*)(pq1 + o);
            fma2(acc0[2], p0, w.x); fma2(acc0[3], p0, w.y);
            fma2(acc1[2], p1, w.x); fma2(acc1[3], p1, w.y);
            w = *(const ulonglong2*)(pq2 + o);
            fma2(acc0[4], p0, w.x); fma2(acc0[5], p0, w.y);
            fma2(acc1[4], p1, w.x); fma2(acc1[5], p1, w.y);
            w = *(const ulonglong2*)(pq3 + o);
            fma2(acc0[6], p0, w.x); fma2(acc0[7], p0, w.y);
            fma2(acc1[6], p1, w.x); fma2(acc1[7], p1, w.y);
        }
    }

    // ---- Reduce across si lanes (identical to R8) -----------------------
    if constexpr (MS >= 2) {
        u64 t0[8], t1[8];
        #pragma unroll
        for (int u = 0; u < 8; u++) {
            t0[u] = __shfl_xor_sync(0xffffffffu, acc0[u ^ 2], 1);
            t1[u] = __shfl_xor_sync(0xffffffffu, acc1[u ^ 2], 1);
        }
        #pragma unroll
        for (int u = 0; u < 8; u++) { acc0[u] = add2(acc0[u], t0[u]); acc1[u] = add2(acc1[u], t1[u]); }
    }
    if constexpr (MS >= 4) {
        u64 t0[8], t1[8];
        #pragma unroll
        for (int u = 0; u < 8; u++) {
            t0[u] = __shfl_xor_sync(0xffffffffu, acc0[u ^ 4], 2);
            t1[u] = __shfl_xor_sync(0xffffffffu, acc1[u ^ 4], 2);
        }
        #pragma unroll
        for (int u = 0; u < 8; u++) { acc0[u] = add2(acc0[u], t0[u]); acc1[u] = add2(acc1[u], t1[u]); }
    }
    if constexpr (MS == 8) {
        u64 t0[8], t1[8];
        #pragma unroll
        for (int u = 0; u < 8; u++) {
            t0[u] = __shfl_xor_sync(0xffffffffu, acc0[u], 4);
            t1[u] = __shfl_xor_sync(0xffffffffu, acc1[u], 4);
        }
        #pragma unroll
        for (int u = 0; u < 8; u++) { acc0[u] = add2(acc0[u], t0[u]); acc1[u] = add2(acc1[u], t1[u]); }
    }

    // ---- Store (identical to R8) ----------------------------------------
    float* o0p = hout + ((size_t)n0 * F_out + f) * 16;
    float* o1p = hout + ((size_t)n1 * F_out + f) * 16;
    if constexpr (MS == 1) {
        #pragma unroll
        for (int qq = 0; qq < 4; qq++) {
            store_quad(o0p + 4 * qq, acc0[2 * qq], acc0[2 * qq + 1], base0);
            store_quad(o1p + 4 * qq, acc1[2 * qq], acc1[2 * qq + 1], base1);
        }
    } else if constexpr (MS == 2) {
        const int ka = si ? 12 : 0, kb = si ? 8 : 4;
        u64 A0 = si ? acc0[4] : acc0[0], A1 = si ? acc0[5] : acc0[1];
        u64 B0 = si ? acc0[6] : acc0[2], B1 = si ? acc0[7] : acc0[3];
        store_quad(o0p + ka, A0, A1, base0);
        store_quad(o0p + kb, B0, B1, base0);
        u64 C0 = si ? acc1[4] : acc1[0], C1 = si ? acc1[5] : acc1[1];
        u64 D0 = si ? acc1[6] : acc1[2], D1 = si ? acc1[7] : acc1[3];
        store_quad(o1p + ka, C0, C1, base1);
        store_quad(o1p + kb, D0, D1, base1);
    } else if constexpr (MS == 4) {
        store_quad(o0p + 4 * si, acc0[0], acc0[1], base0);
        store_quad(o1p + 4 * si, acc1[0], acc1[1], base1);
    } else { // MS == 8
        if (si < 4) {
            store_quad(o0p + 4 * si, acc0[0], acc0[1], base0);
            store_quad(o1p + 4 * si, acc1[0], acc1[1], base1);
        }
    }
}

// ---------------------------------------------------------------------------
// Root. Block per n (512 blocks, 32 threads), warp-shfl reduce.
// ---------------------------------------------------------------------------
__global__ void __launch_bounds__(32) root_kernel(
    const float* __restrict__ h4, const float* __restrict__ Wroot,
    float* __restrict__ out)
{
    const int n = blockIdx.x;
    const int t = threadIdx.x;
    const float4* hp = (const float4*)(h4 + (size_t)n * 512);

    float4 a = make_float4(0.f, 0.f, 0.f, 0.f);
    #pragma unroll
    for (int r = 0; r < 4; r++) {
        float4 q = hp[t + 32 * r];
        a.x += q.x; a.y += q.y; a.z += q.z; a.w += q.w;
    }
    #pragma unroll
    for (int st = 4; st <= 16; st <<= 1) {
        a.x += __shfl_xor_sync(0xffffffffu, a.x, st);
        a.y += __shfl_xor_sync(0xffffffffu, a.y, st);
        a.z += __shfl_xor_sync(0xffffffffu, a.z, st);
        a.w += __shfl_xor_sync(0xffffffffu, a.w, st);
    }
    __shared__ float sred[16];
    if (t < 4) { sred[4*t] = a.x; sred[4*t+1] = a.y; sred[4*t+2] = a.z; sred[4*t+3] = a.w; }
    __syncwarp();

    if (t == 0) {
        float w[16];
        #pragma unroll
        for (int k = 0; k < 16; k++) w[k] = Wroot[k];
        float wm = w[0];
        #pragma unroll
        for (int k = 1; k < 16; k++) wm = fmaxf(wm, w[k]);
        float Z = 0.f;
        #pragma unroll
        for (int k = 0; k < 16; k++) Z += __expf(w[k] - wm);
        const float lz = __logf(Z) + wm;

        float tv[16];
        float tm = -1e30f;
        #pragma unroll
        for (int k = 0; k < 16; k++) {
            tv[k] = sred[k] + w[k] - lz;
            tm = fmaxf(tm, tv[k]);
        }
        float ss = 0.f;
        #pragma unroll
        for (int k = 0; k < 16; k++) ss += __expf(tv[k] - tm);
        out[n] = __logf(ss) + tm;
    }
}

// ---------------------------------------------------------------------------
extern "C" void kernel_launch(void* const* d_in, const int* in_sizes, int n_in,
                              void* d_out, int out_size)
{
    const float* x  = (const float*)d_in[0];
    const float* W1 = (const float*)d_in[1];
    const float* W2 = (const float*)d_in[2];
    const float* W3 = (const float*)d_in[3];
    const float* W4 = (const float*)d_in[4];
    const float* Wr = (const float*)d_in[5];
    float* out = (float*)d_out;

    float *hA, *hB;
    cudaGetSymbolAddress((void**)&hA, g_hA);
    cudaGetSymbolAddress((void**)&hB, g_hB);

    // smem = (4224 + NSL*34) floats; all < 48KB.
    const size_t sm1 = (4224 + 128 * 34) * 4;  // 34304
    const size_t sm2 = (4224 +  64 * 34) * 4;  // 25600
    const size_t sm4 = (4224 +  32 * 34) * 4;  // 21248
    const size_t sm8 = (4224 +  16 * 34) * 4;  // 19072

    // R8 layer shapes (best): 512 blocks each, NT=2, fused normalized softmax.
    layer_kernel<1><<<dim3(256, 2),  128, sm1>>>(x,  W1, hA, 512);
    layer_kernel<2><<<dim3(128, 4),  128, sm2>>>(hA, W2, hB, 256);
    layer_kernel<4><<<dim3(64, 8),   128, sm4>>>(hB, W3, hA, 128);
    layer_kernel<8><<<dim3(32, 16),  128, sm8>>>(hA, W4, hB, 64);

    root_kernel<<<512, 32>>>(hB, Wr, out);
}